// round 1
// baseline (speedup 1.0000x reference)
#include <cuda_runtime.h>

#define NC 19
#define HW (512 * 512)
#define BATCH 8
#define SMOOTHF 1e-5f
#define IGNORE_IDX 255

// scratch: [0..151] = intersection(b,c), [152..303] = union(b,c)
__device__ float g_acc[2 * BATCH * NC];

__global__ void zero_acc_kernel() {
    if (threadIdx.x < 2 * BATCH * NC) g_acc[threadIdx.x] = 0.0f;
}

// grid: (16, BATCH), block: 512. Each block covers 16384 consecutive pixels of
// one batch image; each thread handles 32 pixels (stride 512, coalesced).
__global__ __launch_bounds__(512) void dice_main_kernel(
    const float* __restrict__ pred, const int* __restrict__ target) {
    const int b    = blockIdx.y;
    const int base = blockIdx.x * (HW / 16);
    const float* pb = pred + (size_t)b * NC * HW;
    const int*   tb = target + (size_t)b * HW;

    float accI[NC], accU[NC];
#pragma unroll
    for (int c = 0; c < NC; c++) { accI[c] = 0.0f; accU[c] = 0.0f; }

#pragma unroll 1
    for (int k = 0; k < 32; k++) {
        const int px = base + k * 512 + threadIdx.x;
        const int t  = tb[px];
        float x[NC];
#pragma unroll
        for (int c = 0; c < NC; c++) x[c] = pb[c * HW + px];  // 19 batched LDGs

        if (t == IGNORE_IDX) continue;  // masked pixel contributes nothing

        float m = x[0];
#pragma unroll
        for (int c = 1; c < NC; c++) m = fmaxf(m, x[c]);
        float s = 0.0f;
#pragma unroll
        for (int c = 0; c < NC; c++) { x[c] = __expf(x[c] - m); s += x[c]; }
        const float r = __frcp_rn(s);

#pragma unroll
        for (int c = 0; c < NC; c++) {
            const float p   = x[c] * r;
            const bool  hit = (c == t);
            accI[c] += hit ? p : 0.0f;          // pm * one_hot
            accU[c] += hit ? (p + 1.0f) : p;    // pm.sum + one_hot.sum
        }
    }

    // warp butterfly reduction of the 38 accumulators
#pragma unroll
    for (int c = 0; c < NC; c++) {
#pragma unroll
        for (int o = 16; o > 0; o >>= 1) {
            accI[c] += __shfl_xor_sync(0xffffffffu, accI[c], o);
            accU[c] += __shfl_xor_sync(0xffffffffu, accU[c], o);
        }
    }

    __shared__ float sh[16][2 * NC];
    const int warp = threadIdx.x >> 5;
    if ((threadIdx.x & 31) == 0) {
#pragma unroll
        for (int c = 0; c < NC; c++) {
            sh[warp][c]      = accI[c];
            sh[warp][NC + c] = accU[c];
        }
    }
    __syncthreads();

    // first 38 threads: cross-warp reduce + one global atomic each
    if (threadIdx.x < 2 * NC) {
        float v = 0.0f;
#pragma unroll
        for (int w = 0; w < 16; w++) v += sh[w][threadIdx.x];
        const bool isI = threadIdx.x < NC;
        const int  c   = isI ? threadIdx.x : threadIdx.x - NC;
        float* dst = isI ? &g_acc[b * NC + c] : &g_acc[BATCH * NC + b * NC + c];
        atomicAdd(dst, v);
    }
}

__global__ void finalize_kernel(float* __restrict__ out) {
    __shared__ float sh[BATCH * NC];
    const int i = threadIdx.x;
    if (i < BATCH * NC) {
        const float I = g_acc[i];
        const float U = g_acc[BATCH * NC + i];
        sh[i] = 1.0f - (2.0f * I + SMOOTHF) / (U + SMOOTHF);
    }
    __syncthreads();
    if (i == 0) {
        float s = 0.0f;
        for (int j = 0; j < BATCH * NC; j++) s += sh[j];
        out[0] = s / (float)(BATCH * NC);
    }
}

extern "C" void kernel_launch(void* const* d_in, const int* in_sizes, int n_in,
                              void* d_out, int out_size) {
    const float* pred   = (const float*)d_in[0];
    const int*   target = (const int*)d_in[1];
    (void)in_sizes; (void)n_in; (void)out_size;

    zero_acc_kernel<<<1, 2 * BATCH * NC>>>();
    dice_main_kernel<<<dim3(16, BATCH), 512>>>(pred, target);
    finalize_kernel<<<1, 256>>>((float*)d_out);
}

// round 3
// speedup vs baseline: 1.2644x; 1.2644x over previous
#include <cuda_runtime.h>

#define NC 19
#define HW (512 * 512)
#define BATCH 8
#define TPB 256
#define PAIRS_PER_THREAD 8
#define NUM_X (HW / 2 / (TPB * PAIRS_PER_THREAD))  // 64
#define N_CTAS (NUM_X * BATCH)                     // 512
#define SMOOTHF 1e-5f
#define IGNORE_IDX 255

// zero-initialized at module load; the last CTA re-zeros after reading so the
// kernel is deterministic across graph replays. No allocations anywhere.
__device__ float        g_acc[2 * BATCH * NC];  // [0:152)=inter(b,c), [152:304)=union(b,c)
__device__ unsigned int g_count;

__global__ __launch_bounds__(TPB, 2) void dice_fused_kernel(
    const float* __restrict__ pred, const int* __restrict__ target,
    float* __restrict__ out) {
    const int b = blockIdx.y;
    // pair index of this thread's first pixel-pair
    const int pair0 = blockIdx.x * (TPB * PAIRS_PER_THREAD) + threadIdx.x;
    const float2* pb = (const float2*)(pred + (size_t)b * NC * HW);
    const int2*   tb = (const int2*)(target + (size_t)b * HW);

    float accI[NC], accU[NC];
#pragma unroll
    for (int c = 0; c < NC; c++) { accI[c] = 0.0f; accU[c] = 0.0f; }

#pragma unroll 1
    for (int k = 0; k < PAIRS_PER_THREAD; k++) {
        const int pr = pair0 + k * TPB;
        const int2 t2 = __ldcs(tb + pr);

        float2 e[NC];
#pragma unroll
        for (int c = 0; c < NC; c++)
            e[c] = __ldcs(pb + (size_t)c * (HW / 2) + pr);  // 19 batched LDG.64

        float s0 = 0.0f, s1 = 0.0f;
#pragma unroll
        for (int c = 0; c < NC; c++) {
            e[c].x = __expf(e[c].x); s0 += e[c].x;
            e[c].y = __expf(e[c].y); s1 += e[c].y;
        }
        const float r0 = __fdividef(1.0f, s0);
        const float r1 = __fdividef(1.0f, s1);

        const bool v0 = (t2.x != IGNORE_IDX);
        const bool v1 = (t2.y != IGNORE_IDX);
#pragma unroll
        for (int c = 0; c < NC; c++) {
            if (v0) {
                const float p = e[c].x * r0;
                accU[c] += p;
                if (c == t2.x) { accI[c] += p; accU[c] += 1.0f; }
            }
            if (v1) {
                const float p = e[c].y * r1;
                accU[c] += p;
                if (c == t2.y) { accI[c] += p; accU[c] += 1.0f; }
            }
        }
    }

    // warp butterfly over the 38 accumulators
#pragma unroll
    for (int c = 0; c < NC; c++) {
#pragma unroll
        for (int o = 16; o > 0; o >>= 1) {
            accI[c] += __shfl_xor_sync(0xffffffffu, accI[c], o);
            accU[c] += __shfl_xor_sync(0xffffffffu, accU[c], o);
        }
    }

    __shared__ float sh[TPB / 32][2 * NC];
    const int warp = threadIdx.x >> 5;
    if ((threadIdx.x & 31) == 0) {
#pragma unroll
        for (int c = 0; c < NC; c++) {
            sh[warp][c]      = accI[c];
            sh[warp][NC + c] = accU[c];
        }
    }
    __syncthreads();

    if (threadIdx.x < 2 * NC) {
        float v = 0.0f;
#pragma unroll
        for (int w = 0; w < TPB / 32; w++) v += sh[w][threadIdx.x];
        const bool isI = threadIdx.x < NC;
        const int  c   = isI ? threadIdx.x : threadIdx.x - NC;
        float* dst = isI ? &g_acc[b * NC + c] : &g_acc[BATCH * NC + b * NC + c];
        atomicAdd(dst, v);
        __threadfence();  // partials globally visible before the ticket bump
    }
    __syncthreads();

    __shared__ unsigned int s_ticket;
    if (threadIdx.x == 0) s_ticket = atomicAdd(&g_count, 1u);
    __syncthreads();

    if (s_ticket == (unsigned int)(N_CTAS - 1)) {
        // last CTA: every other CTA's atomics are visible (fence + ticket order)
        __shared__ float sd[BATCH * NC];
        const int i = threadIdx.x;
        if (i < BATCH * NC) {
            const float I = g_acc[i];
            const float U = g_acc[BATCH * NC + i];
            sd[i] = 1.0f - (2.0f * I + SMOOTHF) / (U + SMOOTHF);
        }
        __syncthreads();  // finish reading g_acc before re-zeroing
        for (int j = i; j < 2 * BATCH * NC; j += TPB) g_acc[j] = 0.0f;
        if (i == 0) {
            float ssum = 0.0f;
            for (int j = 0; j < BATCH * NC; j++) ssum += sd[j];
            out[0]  = ssum / (float)(BATCH * NC);
            g_count = 0u;  // reset for next graph replay
        }
    }
}

extern "C" void kernel_launch(void* const* d_in, const int* in_sizes, int n_in,
                              void* d_out, int out_size) {
    const float* pred   = (const float*)d_in[0];
    const int*   target = (const int*)d_in[1];
    (void)in_sizes; (void)n_in; (void)out_size;

    dice_fused_kernel<<<dim3(NUM_X, BATCH), TPB>>>(pred, target, (float*)d_out);
}

// round 4
// speedup vs baseline: 1.3944x; 1.1029x over previous
#include <cuda_runtime.h>

#define NC 19
#define HW (512 * 512)
#define BATCH 8
#define TPB 256
#define NWARP (TPB / 32)
#define PAIRS 4
#define NUM_X (HW / 2 / (TPB * PAIRS))  // 128
#define N_CTAS (NUM_X * BATCH)          // 1024
#define SMOOTHF 1e-5f
#define IGNORE_IDX 255

// zero-initialized at module load; last CTA re-zeros after reading so the
// kernel is deterministic across graph replays. No allocations anywhere.
__device__ float        g_acc[2 * BATCH * NC];  // [0:152)=inter(b,c), [152:304)=union(b,c)
__device__ unsigned int g_count;

__global__ __launch_bounds__(TPB, 3) void dice_fused_kernel(
    const float* __restrict__ pred, const int* __restrict__ target,
    float* __restrict__ out) {
    const int b     = blockIdx.y;
    const int pair0 = blockIdx.x * (TPB * PAIRS) + threadIdx.x;
    const float2* pb = (const float2*)(pred + (size_t)b * NC * HW);
    const int2*   tb = (const int2*)(target + (size_t)b * HW);
    const int warp = threadIdx.x >> 5;
    const int lane = threadIdx.x & 31;

    // per-warp bins: intersection and one-hot count, indexed by target class
    __shared__ float sI[NWARP][NC];
    __shared__ float sCnt[NWARP][NC];
    if (lane < NC) { sI[warp][lane] = 0.0f; sCnt[warp][lane] = 0.0f; }
    __syncwarp();

    float accU[NC];
#pragma unroll
    for (int c = 0; c < NC; c++) accU[c] = 0.0f;

#pragma unroll 1
    for (int k = 0; k < PAIRS; k++) {
        const int pr  = pair0 + k * TPB;
        const int2 t2 = __ldcs(tb + pr);

        float2 e[NC];
#pragma unroll
        for (int c = 0; c < NC; c++)
            e[c] = __ldcs(pb + (size_t)c * (HW / 2) + pr);  // 19 batched LDG.64

        float s0 = 0.0f, s1 = 0.0f;
#pragma unroll
        for (int c = 0; c < NC; c++) {
            e[c].x = __expf(e[c].x); s0 += e[c].x;
            e[c].y = __expf(e[c].y); s1 += e[c].y;
        }
        const bool v0 = (t2.x != IGNORE_IDX);
        const bool v1 = (t2.y != IGNORE_IDX);
        // r==0 for ignored pixels makes every contribution vanish (branchless)
        const float r0 = v0 ? __fdividef(1.0f, s0) : 0.0f;
        const float r1 = v1 ? __fdividef(1.0f, s1) : 0.0f;

        float et0 = 0.0f, et1 = 0.0f;
#pragma unroll
        for (int c = 0; c < NC; c++) {
            accU[c] = fmaf(e[c].x, r0, accU[c]);  // Σ pm (masked via r)
            accU[c] = fmaf(e[c].y, r1, accU[c]);
            if (c == t2.x) et0 = e[c].x;          // FSEL: e at target class
            if (c == t2.y) et1 = e[c].y;
        }
        const int tc0 = v0 ? t2.x : 0;
        const int tc1 = v1 ? t2.y : 0;
        atomicAdd(&sI[warp][tc0], et0 * r0);      // intersection (0 if masked)
        atomicAdd(&sI[warp][tc1], et1 * r1);
        atomicAdd(&sCnt[warp][tc0], v0 ? 1.0f : 0.0f);  // one-hot sum
        atomicAdd(&sCnt[warp][tc1], v1 ? 1.0f : 0.0f);
    }

    // butterfly-reduce the 19 union accumulators within each warp
#pragma unroll
    for (int c = 0; c < NC; c++) {
#pragma unroll
        for (int o = 16; o > 0; o >>= 1)
            accU[c] += __shfl_xor_sync(0xffffffffu, accU[c], o);
    }

    __shared__ float shU[NWARP][NC];
    if (lane == 0) {
#pragma unroll
        for (int c = 0; c < NC; c++) shU[warp][c] = accU[c];
    }
    __syncthreads();

    // disjoint thread ranges: inter, one-hot->union, pm-sum->union
    float* const g_union = &g_acc[BATCH * NC];
    if (threadIdx.x < NC) {
        const int c = threadIdx.x;
        float v = 0.0f;
#pragma unroll
        for (int w = 0; w < NWARP; w++) v += sI[w][c];
        atomicAdd(&g_acc[b * NC + c], v);
    } else if (threadIdx.x >= 32 && threadIdx.x < 32 + NC) {
        const int c = threadIdx.x - 32;
        float v = 0.0f;
#pragma unroll
        for (int w = 0; w < NWARP; w++) v += sCnt[w][c];
        atomicAdd(&g_union[b * NC + c], v);
    } else if (threadIdx.x >= 64 && threadIdx.x < 64 + NC) {
        const int c = threadIdx.x - 64;
        float v = 0.0f;
#pragma unroll
        for (int w = 0; w < NWARP; w++) v += shU[w][c];
        atomicAdd(&g_union[b * NC + c], v);
    }
    __threadfence();  // partials visible before the ticket bump
    __syncthreads();

    __shared__ unsigned int s_ticket;
    if (threadIdx.x == 0) s_ticket = atomicAdd(&g_count, 1u);
    __syncthreads();

    if (s_ticket == (unsigned int)(N_CTAS - 1)) {
        // last CTA: all other CTAs' atomics visible (fence + ticket order)
        __shared__ float sd[BATCH * NC];
        const int i = threadIdx.x;
        if (i < BATCH * NC) {
            const float I = g_acc[i];
            const float U = g_acc[BATCH * NC + i];
            sd[i] = 1.0f - (2.0f * I + SMOOTHF) / (U + SMOOTHF);
        }
        __syncthreads();  // finish reading g_acc before re-zeroing
        for (int j = i; j < 2 * BATCH * NC; j += TPB) g_acc[j] = 0.0f;
        if (i == 0) {
            float ssum = 0.0f;
            for (int j = 0; j < BATCH * NC; j++) ssum += sd[j];
            out[0]  = ssum / (float)(BATCH * NC);
            g_count = 0u;  // reset for next graph replay
        }
    }
}

extern "C" void kernel_launch(void* const* d_in, const int* in_sizes, int n_in,
                              void* d_out, int out_size) {
    const float* pred   = (const float*)d_in[0];
    const int*   target = (const int*)d_in[1];
    (void)in_sizes; (void)n_in; (void)out_size;

    dice_fused_kernel<<<dim3(NUM_X, BATCH), TPB>>>(pred, target, (float*)d_out);
}